// round 17
// baseline (speedup 1.0000x reference)
#include <cuda_runtime.h>
#include <cuda_fp16.h>
#include <math.h>

// ---------------- problem constants ----------------
#define Dm   1024
#define Hh   16
#define DH   64
#define DFF  4096
#define DC   768
#define Tt   2048
#define Bb   2
#define Cc   77
#define MX   4096          // Bb*Tt rows of x

// ---------------- scratch (static device arrays; no allocs) ----------------
__device__ __half g_lnH  [(size_t)MX * Dm];
__device__ __half g_qkvH [(size_t)MX * 3 * Dm];
__device__ __half g_attnH[(size_t)MX * Dm];
__device__ __half g_qcaH [(size_t)MX * Dm];
__device__ __half g_kvcaH[(size_t)Bb * Cc * 2 * Dm];
__device__ __half g_ffH  [(size_t)MX * DFF];
__device__ float  g_x1   [(size_t)MX * Dm];
__device__ float  g_x2   [(size_t)MX * Dm];
__device__ __half g_wh   [(size_t)16400000];   // transposed half weights + cond

// weight-scratch offsets (elements)
#define SZ_QKV  (Dm*3*Dm)
#define SZ_PSA  (Dm*Dm)
#define SZ_QCA  (Dm*Dm)
#define SZ_KVCA (DC*2*Dm)
#define SZ_PCA  (Dm*Dm)
#define SZ_FF1  (Dm*DFF)
#define SZ_FF2  (DFF*Dm)
#define SZ_COND (Bb*Cc*DC)
#define OW_QKV   0
#define OW_PSA   (OW_QKV + SZ_QKV)
#define OW_QCA   (OW_PSA + SZ_PSA)
#define OW_KVCA  (OW_QCA + SZ_QCA)
#define OW_PCA   (OW_KVCA + SZ_KVCA)
#define OW_FF1   (OW_PCA + SZ_PCA)
#define OW_FF2   (OW_FF1 + SZ_FF1)
#define OW_COND  (OW_FF2 + SZ_FF2)

// prep tile ranges (32x32 transpose tiles per matrix)
#define TQKV  3072
#define TPSA  (TQKV + 1024)
#define TQCA  (TPSA + 1024)
#define TKVCA (TQCA + 1536)
#define TPCA  (TKVCA + 1024)
#define TFF1  (TPCA + 4096)
#define TFF2  (TFF1 + 4096)
#define TCOND (TFF2 + (SZ_COND / 256))

// ---------------- helpers ----------------
__device__ __forceinline__ unsigned hpack(float a, float b) {
    __half2 h = __floats2half2_rn(a, b);
    return *(unsigned*)&h;
}

__device__ __forceinline__ void mma_f16(float c[4],
    unsigned a0, unsigned a1, unsigned a2, unsigned a3,
    unsigned b0, unsigned b1)
{
    asm volatile(
        "mma.sync.aligned.m16n8k16.row.col.f32.f16.f16.f32 "
        "{%0,%1,%2,%3}, {%4,%5,%6,%7}, {%8,%9}, {%0,%1,%2,%3};\n"
        : "+f"(c[0]), "+f"(c[1]), "+f"(c[2]), "+f"(c[3])
        : "r"(a0), "r"(a1), "r"(a2), "r"(a3), "r"(b0), "r"(b1));
}

#define LDM_X4(r0,r1,r2,r3,addr) \
    asm volatile("ldmatrix.sync.aligned.m8n8.x4.shared.b16 {%0,%1,%2,%3}, [%4];" \
        : "=r"(r0),"=r"(r1),"=r"(r2),"=r"(r3) : "r"(addr))
#define LDM_X4T(r0,r1,r2,r3,addr) \
    asm volatile("ldmatrix.sync.aligned.m8n8.x4.trans.shared.b16 {%0,%1,%2,%3}, [%4];" \
        : "=r"(r0),"=r"(r1),"=r"(r2),"=r"(r3) : "r"(addr))

__device__ __forceinline__ void cpa16(unsigned dst, const void* src, bool pred) {
    int sz = pred ? 16 : 0;
    asm volatile("cp.async.cg.shared.global [%0], [%1], 16, %2;\n"
                 :: "r"(dst), "l"(src), "r"(sz));
}
__device__ __forceinline__ void cpa16u(unsigned dst, const void* src) {
    asm volatile("cp.async.cg.shared.global [%0], [%1], 16;\n"
                 :: "r"(dst), "l"(src));
}
__device__ __forceinline__ void cpa_commit() {
    asm volatile("cp.async.commit_group;\n");
}
template<int N>
__device__ __forceinline__ void cpa_wait() {
    asm volatile("cp.async.wait_group %0;\n" :: "n"(N));
}

// ---------------- merged prep: all weight transposes + cond convert ----------------
__global__ __launch_bounds__(256) void prep_all(
    const float* __restrict__ wqkv, const float* __restrict__ wpsa,
    const float* __restrict__ wqca, const float* __restrict__ wkvca,
    const float* __restrict__ wpca, const float* __restrict__ wff1,
    const float* __restrict__ wff2, const float* __restrict__ cond,
    __half* __restrict__ dst)
{
    int b = blockIdx.x;
    int tid = threadIdx.x;

    if (b >= TFF2) {
        int base = (b - TFF2) * 256 + tid;
        if (base < SZ_COND) dst[OW_COND + base] = __float2half(cond[base]);
        return;
    }

    const float* src; __half* d; int K, N; int tile;
    if      (b < TQKV)  { src = wqkv;  d = dst + OW_QKV;  K = Dm;  N = 3*Dm; tile = b; }
    else if (b < TPSA)  { src = wpsa;  d = dst + OW_PSA;  K = Dm;  N = Dm;   tile = b - TQKV; }
    else if (b < TQCA)  { src = wqca;  d = dst + OW_QCA;  K = Dm;  N = Dm;   tile = b - TPSA; }
    else if (b < TKVCA) { src = wkvca; d = dst + OW_KVCA; K = DC;  N = 2*Dm; tile = b - TQCA; }
    else if (b < TPCA)  { src = wpca;  d = dst + OW_PCA;  K = Dm;  N = Dm;   tile = b - TKVCA; }
    else if (b < TFF1)  { src = wff1;  d = dst + OW_FF1;  K = Dm;  N = DFF;  tile = b - TPCA; }
    else                { src = wff2;  d = dst + OW_FF2;  K = DFF; N = Dm;   tile = b - TFF1; }

    int tX = N >> 5;
    int bx = (tile % tX) * 32, by = (tile / tX) * 32;
    __shared__ float t[32][33];
    int tx = tid & 31, ty = tid >> 5;
    #pragma unroll
    for (int j = 0; j < 32; j += 8)
        t[ty + j][tx] = src[(long)(by + ty + j) * N + bx + tx];
    __syncthreads();
    #pragma unroll
    for (int j = 0; j < 32; j += 8)
        d[(long)(bx + ty + j) * K + by + tx] = __float2half(t[tx][ty + j]);
}

// ---------------- reductions ----------------
__device__ __forceinline__ float block_sum(float v, float* sh) {
    #pragma unroll
    for (int o = 16; o > 0; o >>= 1) v += __shfl_xor_sync(0xffffffffu, v, o);
    int w = threadIdx.x >> 5;
    if ((threadIdx.x & 31) == 0) sh[w] = v;
    __syncthreads();
    if (threadIdx.x < 32) {
        float t = (threadIdx.x < 8) ? sh[threadIdx.x] : 0.f;
        #pragma unroll
        for (int o = 4; o > 0; o >>= 1) t += __shfl_xor_sync(0xffffffffu, t, o);
        if (threadIdx.x == 0) sh[0] = t;
    }
    __syncthreads();
    float r = sh[0];
    __syncthreads();
    return r;
}

// ---------------- LayerNorm (half output) ----------------
__global__ __launch_bounds__(256) void ln_kernel(
    const float* __restrict__ x, const float* __restrict__ g,
    const float* __restrict__ b, __half* __restrict__ out)
{
    __shared__ float sh[8];
    long row = blockIdx.x;
    const float4* xr = (const float4*)(x + row * Dm);
    int tid = threadIdx.x;
    float4 v = xr[tid];
    float s = v.x + v.y + v.z + v.w;
    s = block_sum(s, sh);
    float mean = s * (1.0f / Dm);
    float dx = v.x - mean, dy = v.y - mean, dz = v.z - mean, dw = v.w - mean;
    float s2 = dx*dx + dy*dy + dz*dz + dw*dw;
    s2 = block_sum(s2, sh);
    float rstd = rsqrtf(s2 * (1.0f / Dm) + 1e-5f);
    float4 gg = ((const float4*)g)[tid];
    float4 bbv = ((const float4*)b)[tid];
    uint2 u;
    u.x = hpack(dx * rstd * gg.x + bbv.x, dy * rstd * gg.y + bbv.y);
    u.y = hpack(dz * rstd * gg.z + bbv.z, dw * rstd * gg.w + bbv.w);
    ((uint2*)(out + row * Dm))[tid] = u;
}

// ================= fused flash attention (fp16, h2exp softmax) =============
#define FBQ 128
#define FBK2 128
#define FST 36
#define FSMEM ((FBQ + FBK2 + FBK2) * FST * 4)     // 55296 B

__global__ __launch_bounds__(256, 2) void flash_kernel(
    const __half* __restrict__ Qp, const __half* __restrict__ Kp,
    const __half* __restrict__ Vp, __half* __restrict__ Op,
    int Tq, int Tk, int ldq, int ldk, int ldo,
    long sQb, long sQh, long sKb, long sKh, long sOb, long sOh,
    int Hn, int causal)
{
    extern __shared__ unsigned fsm[];
    unsigned* Qs = fsm;
    unsigned* Ks = fsm + FBQ * FST;
    unsigned* Vs = Ks + FBK2 * FST;
    unsigned sbase = (unsigned)__cvta_generic_to_shared(fsm);

    int z = blockIdx.z, zb = z / Hn, zh = z - zb * Hn;
    Qp += zb * sQb + zh * sQh;
    Kp += zb * sKb + zh * sKh;
    Vp += zb * sKb + zh * sKh;
    Op += zb * sOb + zh * sOh;

    int tid = threadIdx.x, lane = tid & 31, warp = tid >> 5;
    int gid = lane >> 2, tg = lane & 3;
    int sel = lane & 7, grp = lane >> 3;
    int yb = causal ? ((int)gridDim.y - 1 - (int)blockIdx.y) : (int)blockIdx.y;
    int row0 = yb * FBQ;
    int wrmax = row0 + warp * 16 + 15;

    const __half2 scale2 = __half2half2(__float2half(0.125f));

    #pragma unroll
    for (int it = 0; it < 4; it++) {
        int idx = it * 256 + tid;
        int r = idx >> 3, c8 = (idx & 7) * 8;
        int gr = row0 + r;
        uint4 v = make_uint4(0u, 0u, 0u, 0u);
        if (gr < Tq) v = *(const uint4*)(Qp + (long)gr * ldq + c8);
        __half2* h = (__half2*)&v;
        h[0] = __hmul2(h[0], scale2); h[1] = __hmul2(h[1], scale2);
        h[2] = __hmul2(h[2], scale2); h[3] = __hmul2(h[3], scale2);
        *(uint4*)&Qs[r * FST + c8 / 2] = v;
    }

    unsigned qAddr = sbase + (unsigned)((warp * 16 + sel + ((grp & 1) << 3)) * 144
                                        + ((grp >> 1) << 4));
    unsigned kBase = sbase + FBQ * 144;
    unsigned vBase = kBase + FBK2 * 144;
    unsigned kRow = (unsigned)((sel + ((grp >> 1) << 3)) * 144 + ((grp & 1) << 4));
    unsigned vRow = (unsigned)((sel + ((grp & 1) << 3)) * 144 + ((grp >> 1) << 4));

    int r_0 = row0 + warp * 16 + gid;
    int r_1 = r_0 + 8;

    float m0 = -1e30f, m1 = -1e30f, l0 = 0.f, l1 = 0.f;
    float o[8][4];
    #pragma unroll
    for (int i = 0; i < 8; i++)
        #pragma unroll
        for (int j = 0; j < 4; j++) o[i][j] = 0.f;

    int ntile = causal ? (row0 + FBQ + FBK2 - 1) / FBK2 : (Tk + FBK2 - 1) / FBK2;

    for (int t = 0; t < ntile; t++) {
        int tb = t * FBK2;
        __syncthreads();
        #pragma unroll
        for (int it = 0; it < 4; it++) {
            int idx = it * 256 + tid;
            int r = idx >> 3, c8 = (idx & 7) * 8;
            int gr = tb + r;
            uint4 kv = make_uint4(0u,0u,0u,0u), vv = make_uint4(0u,0u,0u,0u);
            if (gr < Tk) {
                kv = *(const uint4*)(Kp + (long)gr * ldk + c8);
                vv = *(const uint4*)(Vp + (long)gr * ldk + c8);
            }
            *(uint4*)&Ks[r * FST + c8 / 2] = kv;
            *(uint4*)&Vs[r * FST + c8 / 2] = vv;
        }
        __syncthreads();

        #pragma unroll
        for (int sub = 0; sub < 2; sub++) {
            int kvb = tb + sub * 64;
            if (causal && kvb > wrmax) continue;
            if (!causal && kvb >= Tk) continue;
            unsigned kSub = kBase + (unsigned)(sub * 64 * 144);
            unsigned vSub = vBase + (unsigned)(sub * 64 * 144);

            float sacc[8][4];
            #pragma unroll
            for (int i = 0; i < 8; i++)
                #pragma unroll
                for (int j = 0; j < 4; j++) sacc[i][j] = 0.f;

            #pragma unroll
            for (int ks = 0; ks < 4; ks++) {
                unsigned qa0, qa1, qa2, qa3;
                LDM_X4(qa0, qa1, qa2, qa3, qAddr + ks * 32);
                #pragma unroll
                for (int np = 0; np < 4; np++) {
                    unsigned b0, b1, b2, b3;
                    LDM_X4(b0, b1, b2, b3, kSub + np * (16 * 144) + kRow + ks * 32);
                    mma_f16(sacc[2*np],     qa0, qa1, qa2, qa3, b0, b1);
                    mma_f16(sacc[2*np + 1], qa0, qa1, qa2, qa3, b2, b3);
                }
            }

            bool domask = (causal && (kvb + 63 > row0)) || (kvb + 64 > Tk);
            if (domask) {
                #pragma unroll
                for (int ni = 0; ni < 8; ni++) {
                    #pragma unroll
                    for (int s = 0; s < 4; s++) {
                        int col = kvb + ni * 8 + tg * 2 + (s & 1);
                        int r = (s < 2) ? r_0 : r_1;
                        bool ok = (col < Tk) && (!causal || col <= r);
                        if (!ok) sacc[ni][s] = -1e30f;
                    }
                }
            }

            // ---- online softmax: exp computed in half2 (f16x2 MUFU) ----
            float tm0 = -1e30f, tm1 = -1e30f;
            #pragma unroll
            for (int ni = 0; ni < 8; ni++) {
                tm0 = fmaxf(tm0, fmaxf(sacc[ni][0], sacc[ni][1]));
                tm1 = fmaxf(tm1, fmaxf(sacc[ni][2], sacc[ni][3]));
            }
            tm0 = fmaxf(tm0, __shfl_xor_sync(0xffffffffu, tm0, 1));
            tm0 = fmaxf(tm0, __shfl_xor_sync(0xffffffffu, tm0, 2));
            tm1 = fmaxf(tm1, __shfl_xor_sync(0xffffffffu, tm1, 1));
            tm1 = fmaxf(tm1, __shfl_xor_sync(0xffffffffu, tm1, 2));

            float nm0 = fmaxf(m0, tm0), nm1 = fmaxf(m1, tm1);
            float sc0 = __expf(m0 - nm0), sc1 = __expf(m1 - nm1);
            m0 = nm0; m1 = nm1;

            unsigned pfrag[8][2];
            float rs0 = 0.f, rs1 = 0.f;
            #pragma unroll
            for (int ni = 0; ni < 8; ni++) {
                __half2 e01 = h2exp(__floats2half2_rn(sacc[ni][0] - nm0,
                                                      sacc[ni][1] - nm0));
                __half2 e23 = h2exp(__floats2half2_rn(sacc[ni][2] - nm1,
                                                      sacc[ni][3] - nm1));
                pfrag[ni][0] = *(unsigned*)&e01;
                pfrag[ni][1] = *(unsigned*)&e23;
                float2 f01 = __half22float2(e01);
                float2 f23 = __half22float2(e23);
                rs0 += f01.x + f01.y;
                rs1 += f23.x + f23.y;
            }
            rs0 += __shfl_xor_sync(0xffffffffu, rs0, 1);
            rs0 += __shfl_xor_sync(0xffffffffu, rs0, 2);
            rs1 += __shfl_xor_sync(0xffffffffu, rs1, 1);
            rs1 += __shfl_xor_sync(0xffffffffu, rs1, 2);
            l0 = l0 * sc0 + rs0;
            l1 = l1 * sc1 + rs1;

            #pragma unroll
            for (int ni = 0; ni < 8; ni++) {
                o[ni][0] *= sc0; o[ni][1] *= sc0;
                o[ni][2] *= sc1; o[ni][3] *= sc1;
            }

            // ---- O += P @ V  (A-frags are pfrag directly) ----
            #pragma unroll
            for (int ks = 0; ks < 4; ks++) {
                unsigned a0 = pfrag[2*ks][0];
                unsigned a1 = pfrag[2*ks][1];
                unsigned a2 = pfrag[2*ks + 1][0];
                unsigned a3 = pfrag[2*ks + 1][1];
                #pragma unroll
                for (int np = 0; np < 4; np++) {
                    unsigned b0, b1, b2, b3;
                    LDM_X4T(b0, b1, b2, b3, vSub + ks * (16 * 144) + vRow + np * 32);
                    mma_f16(o[2*np],     a0, a1, a2, a3, b0, b1);
                    mma_f16(o[2*np + 1], a0, a1, a2, a3, b2, b3);
                }
            }
        }
    }

    float inv0 = 1.0f / l0, inv1 = 1.0f / l1;
    #pragma unroll
    for (int nj = 0; nj < 8; nj++) {
        int c = nj * 8 + tg * 2;
        if (r_0 < Tq) {
            __half2 w = __floats2half2_rn(o[nj][0] * inv0, o[nj][1] * inv0);
            *(__half2*)(Op + (long)r_0 * ldo + c) = w;
        }
        if (r_1 < Tq) {
            __half2 w = __floats2half2_rn(o[nj][2] * inv1, o[nj][3] * inv1);
            *(__half2*)(Op + (long)r_1 * ldo + c) = w;
        }
    }
}

// ======== fp16 GEMM, 128x128 block, 64x32 warp tile, 2 CTAs/SM (all shapes) ========
#define BM 128
#define QBN 128
#define BKH 32
#define NSTG 4
#define HST 20
#define AW (BM * HST)
#define QBW (QBN * HST)
#define QSTG (AW + QBW)
#define QSMEM (QSTG * NSTG * 4)

template<int EPI>
__global__ __launch_bounds__(256, 2) void hgemm2(
    const __half* __restrict__ A, const __half* __restrict__ Bt,
    const float* __restrict__ bias, const float* __restrict__ Res,
    float* __restrict__ C,
    int M, int N, int K, int lda, int ldbk)
{
    extern __shared__ unsigned dsm[];
    unsigned sbase = (unsigned)__cvta_generic_to_shared(dsm);

    int row0 = blockIdx.y * BM, col0 = blockIdx.x * QBN;
    int tid  = threadIdx.x;
    int lane = tid & 31, warp = tid >> 5;
    int wm = (warp & 1) * 64;
    int wn = (warp >> 1) * 32;
    int gid = lane >> 2, tg = lane & 3;

    int ar = tid >> 1;
    int ha = (tid & 1) * 16;

    auto load_stage = [&](int s, int k0) {
        unsigned abase = sbase + (s * QSTG) * 4;
        unsigned bbase = sbase + (s * QSTG + AW) * 4;
        const __half* asrc = A + (long)(row0 + ar) * lda + k0 + ha;
        bool av = (row0 + ar) < M;
        unsigned adst = abase + (ar * HST + ha / 2) * 4;
        cpa16(adst, asrc, av);
        cpa16(adst + 16, asrc + 8, av);
        const __half* bsrc = Bt + (long)(col0 + ar) * ldbk + k0 + ha;
        unsigned bdst = bbase + (ar * HST + ha / 2) * 4;
        cpa16u(bdst, bsrc);
        cpa16u(bdst + 16, bsrc + 8);
    };

    unsigned aOff = (unsigned)((wm + (lane & 15)) * (HST * 4) + ((lane >> 4) << 4));
    unsigned bOff = (unsigned)(AW * 4 +
        (wn + (lane & 7) + ((lane >> 4) & 1) * 8) * (HST * 4) + (((lane >> 3) & 1) << 4));

    float acc[4][4][4];
    #pragma unroll
    for (int i = 0; i < 4; i++)
        #pragma unroll
        for (int j = 0; j < 4; j++)
            #pragma unroll
            for (int r = 0; r < 4; r++) acc[i][j][r] = 0.f;

    int ntiles = K / BKH;

    #pragma unroll
    for (int s = 0; s < NSTG - 1; s++) {
        if (s < ntiles) load_stage(s, s * BKH);
        cpa_commit();
    }

    for (int t = 0; t < ntiles; t++) {
        cpa_wait<NSTG - 2>();
        __syncthreads();

        int tn = t + NSTG - 1;
        if (tn < ntiles) load_stage(tn % NSTG, tn * BKH);
        cpa_commit();

        int buf = t % NSTG;
        unsigned stg = sbase + (unsigned)(buf * QSTG * 4);
        unsigned aA = stg + aOff;
        unsigned bA = stg + bOff;

        #pragma unroll
        for (int ks = 0; ks < 2; ks++) {
            unsigned kbyte = ks * 32;
            unsigned a[4][4], b[4][2];
            #pragma unroll
            for (int mi = 0; mi < 4; mi++)
                LDM_X4(a[mi][0], a[mi][1], a[mi][2], a[mi][3],
                       aA + mi * (16 * HST * 4) + kbyte);
            #pragma unroll
            for (int np = 0; np < 2; np++) {
                unsigned b0, b1, b2, b3;
                LDM_X4(b0, b1, b2, b3, bA + np * (16 * HST * 4) + kbyte);
                b[2*np][0] = b0;     b[2*np][1] = b1;
                b[2*np + 1][0] = b2; b[2*np + 1][1] = b3;
            }
            #pragma unroll
            for (int mi = 0; mi < 4; mi++)
                #pragma unroll
                for (int ni = 0; ni < 4; ni++)
                    mma_f16(acc[mi][ni], a[mi][0], a[mi][1], a[mi][2], a[mi][3],
                            b[ni][0], b[ni][1]);
        }
    }

    #pragma unroll
    for (int mi = 0; mi < 4; mi++) {
        #pragma unroll
        for (int rr = 0; rr < 2; rr++) {
            int r = row0 + wm + mi * 16 + gid + rr * 8;
            if (r >= M) continue;
            #pragma unroll
            for (int ni = 0; ni < 4; ni++) {
                int c = col0 + wn + ni * 8 + tg * 2;
                float v0 = acc[mi][ni][rr * 2 + 0];
                float v1 = acc[mi][ni][rr * 2 + 1];
                if (EPI & 1) { v0 += bias[c]; v1 += bias[c + 1]; }
                if (EPI & 4) {
                    v0 = 0.5f * v0 * (1.0f + erff(v0 * 0.70710678118654752f));
                    v1 = 0.5f * v1 * (1.0f + erff(v1 * 0.70710678118654752f));
                }
                if (EPI & 2) {
                    float2 rv = *(const float2*)(Res + (long)r * N + c);
                    v0 += rv.x; v1 += rv.y;
                }
                if (EPI & 8) {
                    *(__half2*)((__half*)C + (long)r * N + c) = __floats2half2_rn(v0, v1);
                } else {
                    *(float2*)(C + (long)r * N + c) = make_float2(v0, v1);
                }
            }
        }
    }
}

// ---------------- host side ----------------
static inline dim3 qgrid(int M, int N) {
    return dim3((unsigned)((N + QBN - 1) / QBN), (unsigned)((M + BM - 1) / BM), 1);
}

extern "C" void kernel_launch(void* const* d_in, const int* in_sizes, int n_in,
                              void* d_out, int out_size)
{
    const float* x        = (const float*)d_in[0];
    const float* cond     = (const float*)d_in[1];
    const float* Wqkv     = (const float*)d_in[2];
    const float* Wproj_sa = (const float*)d_in[3];
    const float* bproj_sa = (const float*)d_in[4];
    const float* g1       = (const float*)d_in[5];
    const float* b1       = (const float*)d_in[6];
    const float* Wq_ca    = (const float*)d_in[7];
    const float* Wkv_ca   = (const float*)d_in[8];
    const float* Wproj_ca = (const float*)d_in[9];
    const float* bproj_ca = (const float*)d_in[10];
    const float* g2       = (const float*)d_in[11];
    const float* b2       = (const float*)d_in[12];
    const float* Wff1     = (const float*)d_in[13];
    const float* bff1     = (const float*)d_in[14];
    const float* Wff2     = (const float*)d_in[15];
    const float* bff2     = (const float*)d_in[16];
    const float* g3       = (const float*)d_in[17];
    const float* b3       = (const float*)d_in[18];
    float* out            = (float*)d_out;

    __half *p_ln, *p_qkv, *p_attn, *p_qca, *p_kvca, *p_ff, *p_w;
    float *p_x1, *p_x2;
    cudaGetSymbolAddress((void**)&p_ln,   g_lnH);
    cudaGetSymbolAddress((void**)&p_qkv,  g_qkvH);
    cudaGetSymbolAddress((void**)&p_attn, g_attnH);
    cudaGetSymbolAddress((void**)&p_qca,  g_qcaH);
    cudaGetSymbolAddress((void**)&p_kvca, g_kvcaH);
    cudaGetSymbolAddress((void**)&p_ff,   g_ffH);
    cudaGetSymbolAddress((void**)&p_x1,   g_x1);
    cudaGetSymbolAddress((void**)&p_x2,   g_x2);
    cudaGetSymbolAddress((void**)&p_w,    g_wh);

    static int smem_set = 0;
    if (!smem_set) {
        cudaFuncSetAttribute(flash_kernel, cudaFuncAttributeMaxDynamicSharedMemorySize, FSMEM);
        cudaFuncSetAttribute(hgemm2<3>,  cudaFuncAttributeMaxDynamicSharedMemorySize, QSMEM);
        cudaFuncSetAttribute(hgemm2<8>,  cudaFuncAttributeMaxDynamicSharedMemorySize, QSMEM);
        cudaFuncSetAttribute(hgemm2<13>, cudaFuncAttributeMaxDynamicSharedMemorySize, QSMEM);
        smem_set = 1;
    }

    const long T3D = (long)Tt * 3 * Dm;
    const long TD  = (long)Tt * Dm;
    const long KVb = (long)Cc * 2 * Dm;

    // 0) merged prep
    prep_all<<<TCOND, 256>>>(Wqkv, Wproj_sa, Wq_ca, Wkv_ca,
                             Wproj_ca, Wff1, Wff2, cond, p_w);

    // 1) ln1 = LN(x) -> half
    ln_kernel<<<MX, 256>>>(x, g1, b1, p_ln);

    // 2) qkv = ln1 @ Wqkv
    hgemm2<8><<<qgrid(MX, 3*Dm), 256, QSMEM>>>(
        p_ln, p_w + OW_QKV, nullptr, nullptr, (float*)p_qkv, MX, 3*Dm, Dm, Dm, Dm);

    // 3) fused causal self-attention
    flash_kernel<<<dim3(1, Tt/FBQ, Bb*Hh), 256, FSMEM>>>(
        p_qkv, p_qkv + Dm, p_qkv + 2*Dm, p_attn,
        Tt, Tt, 3*Dm, 3*Dm, Dm,
        T3D, DH, T3D, DH, TD, DH, Hh, 1);

    // 4) x1 = x + attn @ Wproj_sa + b
    hgemm2<3><<<qgrid(MX, Dm), 256, QSMEM>>>(
        p_attn, p_w + OW_PSA, bproj_sa, x, p_x1, MX, Dm, Dm, Dm, Dm);

    // 5) ln2 = LN(x1)
    ln_kernel<<<MX, 256>>>(p_x1, g2, b2, p_ln);

    // 6) q_ca = ln2 @ Wq_ca
    hgemm2<8><<<qgrid(MX, Dm), 256, QSMEM>>>(
        p_ln, p_w + OW_QCA, nullptr, nullptr, (float*)p_qca, MX, Dm, Dm, Dm, Dm);

    // 7) kv_ca = cond_h @ Wkv_ca
    hgemm2<8><<<qgrid(Bb*Cc, 2*Dm), 256, QSMEM>>>(
        p_w + OW_COND, p_w + OW_KVCA, nullptr, nullptr, (float*)p_kvca,
        Bb*Cc, 2*Dm, DC, DC, DC);

    // 8) fused cross-attention
    flash_kernel<<<dim3(1, Tt/FBQ, Bb*Hh), 256, FSMEM>>>(
        p_qca, p_kvca, p_kvca + Dm, p_attn,
        Tt, Cc, Dm, 2*Dm, Dm,
        TD, DH, KVb, DH, TD, DH, Hh, 0);

    // 9) x2 = x1 + ca_out @ Wproj_ca + b
    hgemm2<3><<<qgrid(MX, Dm), 256, QSMEM>>>(
        p_attn, p_w + OW_PCA, bproj_ca, p_x1, p_x2, MX, Dm, Dm, Dm, Dm);

    // 10) ln3 = LN(x2)
    ln_kernel<<<MX, 256>>>(p_x2, g3, b3, p_ln);

    // 11) ffh = gelu(ln3 @ Wff1 + bff1)
    hgemm2<13><<<qgrid(MX, DFF), 256, QSMEM>>>(
        p_ln, p_w + OW_FF1, bff1, nullptr, (float*)p_ff, MX, DFF, Dm, Dm, Dm);

    // 12) out = x2 + ffh @ Wff2 + bff2
    hgemm2<3><<<qgrid(MX, Dm), 256, QSMEM>>>(
        p_ff, p_w + OW_FF2, bff2, p_x2, out, MX, Dm, DFF, DFF, DFF);
}